// round 6
// baseline (speedup 1.0000x reference)
#include <cuda_runtime.h>
#include <cuda_bf16.h>

#define NB 32
#define NA 8400
#define NM 50
#define NC 80
#define NO 85
#define BIGC 1000000000.0f
#define GX 33                  // kassignA blocks along anchors (256 thr)
#define NBLK (GX * NB)         // 1056
#define MAXENT 16384
#define LOSS_BLOCKS 64

// ---- scratch ----
__device__ float g_cost[(size_t)NB * NM * NA];
__device__ float g_iou [(size_t)NB * NM * NA];
__device__ int   g_aidx[NB * NA];      // compact slot -> original anchor
__device__ int   g_slotOf[NB * NA];    // anchor -> compact slot (fg only)
__device__ unsigned long long g_mask[NB * NA];
__device__ float g_pobj[NBLK];
__device__ int g_ngt[NB];
__device__ int g_nfg[NB];              // zero-init; re-zeroed by klossC
__device__ unsigned int g_ent[MAXENT];
__device__ int g_cnt;                  // zero-init; re-zeroed by klossC
__device__ int g_done;                 // zero-init; re-zeroed by klossC
__device__ double g_acc[4];            // zero-init; re-zeroed by klossC

// ---- FMA-pipe transcendentals (keep MUFU free for the per-m loop) ----
__device__ __forceinline__ float fexp(float x) {
    float t = x * 1.442695041f;
    float n = rintf(t);
    float g = fmaf(n, -0.6931471806f, t * 0.6931471806f);
    float p = 1.38888889e-3f;
    p = fmaf(p, g, 8.33333333e-3f);
    p = fmaf(p, g, 4.16666667e-2f);
    p = fmaf(p, g, 0.166666667f);
    p = fmaf(p, g, 0.5f);
    p = fmaf(p, g, 1.0f);
    p = fmaf(p, g, 1.0f);
    return p * __int_as_float(((int)n + 127) << 23);
}
__device__ __forceinline__ float flog(float x) {
    int xi = __float_as_int(x);
    int ei = ((xi >> 23) & 0xff) - 126;
    float m = __int_as_float((xi & 0x007fffff) | 0x3f000000);  // [0.5,1)
    if (m < 0.70710678f) { m += m; ei -= 1; }
    float u = m - 1.0f;
    float z = u * u;
    float pp =  7.0376836292e-2f;
    pp = fmaf(pp, u, -1.1514610310e-1f);
    pp = fmaf(pp, u,  1.1676998740e-1f);
    pp = fmaf(pp, u, -1.2420140846e-1f);
    pp = fmaf(pp, u,  1.4249322787e-1f);
    pp = fmaf(pp, u, -1.6668057665e-1f);
    pp = fmaf(pp, u,  2.0000714765e-1f);
    pp = fmaf(pp, u, -2.4999993993e-1f);
    pp = fmaf(pp, u,  3.3333331174e-1f);
    float r = fmaf(pp * u, z, fmaf(-0.5f, z, u));
    return fmaf((float)ei, 0.69314718056f, r);
}
__device__ __forceinline__ float frsqrt(float x) {
    float r = __int_as_float(0x5f375a86 - (__float_as_int(x) >> 1));
    r = r * fmaf(-0.5f * x, r * r, 1.5f);
    r = r * fmaf(-0.5f * x, r * r, 1.5f);
    r = r * fmaf(-0.5f * x, r * r, 1.5f);
    return r;
}

// -------------------------------------------------------------------------
__global__ void __launch_bounds__(256) kassignA(
        const float* __restrict__ outp,
        const float* __restrict__ xsh,
        const float* __restrict__ ysh,
        const float* __restrict__ est,
        const float* __restrict__ lab) {
    int b = blockIdx.y;
    __shared__ float sl[NM * 5];
    __shared__ int s_nv;
    __shared__ int wcnt[8];
    __shared__ int bbase;
    for (int i = threadIdx.x; i < NM * 5; i += 256)
        sl[i] = lab[b * NM * 5 + i];
    __syncthreads();
    if (threadIdx.x == 0) {
        int n = 0;
        for (int m = 0; m < NM; m++) {
            float s = sl[m*5+0] + sl[m*5+1] + sl[m*5+2] + sl[m*5+3] + sl[m*5+4];
            if (s > 0.0f) n++;
        }
        s_nv = n;
        if (blockIdx.x == 0) g_ngt[b] = n;
    }
    __syncthreads();
    int nv = s_nv;   // valid gts are the prefix [0, nv)

    int tid = threadIdx.x;
    int lane = tid & 31, wid = tid >> 5;
    int a = blockIdx.x * 256 + tid;
    bool act = (a < NA);
    float objbase = 0.0f;

    const float* row = outp + ((size_t)b * NA + a) * NO;
    bool fg = false;
    unsigned long long inboth = 0ull;
    float xc = 0, yc = 0;

    if (act) {
        g_mask[b * NA + a] = 0ull;
        float stride = est[a];
        xc = (xsh[a] + 0.5f) * stride;
        yc = (ysh[a] + 0.5f) * stride;
        float rad = 2.5f * stride;
        float obj = row[4];
        objbase = fmaxf(obj, 0.0f) + __logf(1.0f + __expf(-fabsf(obj)));

        #pragma unroll 1
        for (int m = 0; m < nv; m++) {
            float gx = sl[m*5+0], gy = sl[m*5+1], gw = sl[m*5+2], gh = sl[m*5+3];
            float hw = 0.5f * gw, hh = 0.5f * gh;
            bool ib = (xc > gx - hw) && (gx + hw > xc) && (yc > gy - hh) && (gy + hh > yc);
            bool ic = (xc > gx - rad) && (xc < gx + rad) && (yc > gy - rad) && (yc < gy + rad);
            fg = fg || ib || ic;
            if (ib && ic) inboth |= 1ull << m;
        }
    }

    // ---- block-level compaction of fg anchors ----
    unsigned wm = __ballot_sync(0xffffffffu, fg);
    if (lane == 0) wcnt[wid] = __popc(wm);
    __syncthreads();
    if (tid == 0) {
        int s = 0;
        #pragma unroll
        for (int w = 0; w < 8; w++) { int c = wcnt[w]; wcnt[w] = s; s += c; }
        bbase = (s > 0) ? atomicAdd(&g_nfg[b], s) : 0;
    }
    __syncthreads();
    int slot = bbase + wcnt[wid] + __popc(wm & ((1u << lane) - 1u));

    if (fg) {
        g_aidx[b * NA + slot] = a;
        g_slotOf[b * NA + a] = slot;

        float cx = row[0], cy = row[1], w = row[2], h = row[3], obj = row[4];
        float to = 1.0f + fexp(-obj);
        float q  = frsqrt(to);          // sqrt(sigmoid(obj))
        float lso = -0.5f * flog(to);

        // S = sum_c log(1 - p_c) on the FMA pipe (grouped products of 5)
        float S = 0.0f;
        #pragma unroll 4
        for (int g = 0; g < NC; g += 5) {
            float prod = 1.0f;
            #pragma unroll
            for (int c = 0; c < 5; c++) {
                float x = row[5 + g + c];
                float t = 1.0f + fexp(-x);
                prod *= fmaf(-q, frsqrt(t), 1.0f);
            }
            S += flog(fmaxf(prod, 1e-30f));
        }

        float px1 = cx - 0.5f * w, px2 = cx + 0.5f * w;
        float py1 = cy - 0.5f * h, py2 = cy + 0.5f * h;
        float area_p = w * h;
        #pragma unroll 1
        for (int m = 0; m < nv; m++) {
            size_t off = ((size_t)b * NM + m) * NA + slot;
            float gx = sl[m*5+0], gy = sl[m*5+1], gw = sl[m*5+2], gh = sl[m*5+3];
            float hw = 0.5f * gw, hh = 0.5f * gh;
            float tlx = fmaxf(gx - hw, px1), brx = fminf(gx + hw, px2);
            float tly = fmaxf(gy - hh, py1), bry = fminf(gy + hh, py2);
            float ai = ((tlx < brx) && (tly < bry)) ? (brx - tlx) * (bry - tly) : 0.0f;
            float iouv = ai / (gw * gh + area_p - ai + 1e-16f);
            int c = (int)sl[m*5+4];
            float x = row[5 + c];
            float t = 1.0f + __expf(-x);
            float lg = __logf(t);
            float p = q * __frsqrt_rn(t);
            float lp  = fmaxf(lso - 0.5f * lg, -100.0f);
            float l1p = fmaxf(__logf(1.0f - p), -100.0f);
            float cls_cost = -(lp + S - l1p);
            float extra = ((inboth >> m) & 1ull) ? 0.0f : 100000.0f;
            float cost = cls_cost - 3.0f * __logf(iouv + 1e-8f) + extra;
            g_iou[off] = iouv;
            g_cost[off] = cost;
        }
    }

    #pragma unroll
    for (int o = 16; o > 0; o >>= 1)
        objbase += __shfl_down_sync(0xffffffffu, objbase, o);
    __shared__ float sred[8];
    if (lane == 0) sred[wid] = objbase;
    __syncthreads();
    if (tid == 0) {
        float p = 0;
        #pragma unroll
        for (int wq = 0; wq < 8; wq++) p += sred[wq];
        g_pobj[blockIdx.y * GX + blockIdx.x] = p;
    }
}

// -------------------------------------------------------------------------
// One warp per (b, m): scan compacted columns, warp-local top-10 extraction.
__global__ void __launch_bounds__(128) kselect() {
    int gid = (blockIdx.x * 128 + threadIdx.x) >> 5;
    int lane = threadIdx.x & 31;
    int warp = (threadIdx.x >> 5);
    if (gid >= NB * NM) return;
    int b = gid / NM, m = gid % NM;
    if (m >= g_ngt[b]) return;          // valid gts are the prefix

    int n = g_nfg[b];
    size_t rowbase = ((size_t)b * NM + m) * NA;
    const float* iour  = g_iou  + rowbase;
    const float* costr = g_cost + rowbase;
    const int*   aidxr = g_aidx + b * NA;

    float ti[10], tc[10];
    int   tx[10];
    #pragma unroll
    for (int k = 0; k < 10; k++) { ti[k] = 0.0f; tc[k] = 3.0e38f; tx[k] = 0x7fffffff; }

    for (int i = lane; i < n; i += 32) {
        float v = iour[i];
        float c = costr[i];
        if (v > ti[9]) {
            float cur = v;
            #pragma unroll
            for (int k = 0; k < 10; k++)
                if (cur > ti[k]) { float tmp = ti[k]; ti[k] = cur; cur = tmp; }
        }
        if (c < tc[9]) {
            int ai = aidxr[i];
            float cv = c; int ci = ai;
            #pragma unroll
            for (int k = 0; k < 10; k++) {
                bool sw = (cv < tc[k]) || (cv == tc[k] && ci < tx[k]);
                if (sw) {
                    float tf = tc[k]; tc[k] = cv; cv = tf;
                    int   tn = tx[k]; tx[k] = ci; ci = tn;
                }
            }
        }
    }

    // dump per-lane lists to warp-local shared
    __shared__ float s_v[4][320];
    __shared__ float s_c[4][320];
    __shared__ int   s_x[4][320];
    __shared__ int   s_win[4][10];
    #pragma unroll
    for (int k = 0; k < 10; k++) {
        s_v[warp][lane * 10 + k] = ti[k];
        s_c[warp][lane * 10 + k] = tc[k];
        s_x[warp][lane * 10 + k] = tx[k];
    }
    __syncwarp();

    // ---- phase A: sum of global top-10 ious (10 head-extraction passes) ----
    int pos = 0;
    float ksum = 0.0f;
    #pragma unroll 1
    for (int pass = 0; pass < 10; pass++) {
        float hv = (pos < 10) ? s_v[warp][lane * 10 + pos] : -1.0f;
        float bv = hv; int bl = lane;
        #pragma unroll
        for (int o = 16; o > 0; o >>= 1) {
            float ov = __shfl_xor_sync(0xffffffffu, bv, o);
            int   ol = __shfl_xor_sync(0xffffffffu, bl, o);
            if (ov > bv || (ov == bv && ol < bl)) { bv = ov; bl = ol; }
        }
        ksum += bv;
        if (lane == bl) pos++;
    }
    int dynk = (int)ksum;
    if (dynk < 1) dynk = 1;
    if (dynk > 10) dynk = 10;

    // ---- phase B: dyn_k smallest (cost, anchor-idx) ----
    pos = 0;
    int nsel = 0;
    #pragma unroll 1
    for (int pass = 0; pass < dynk; pass++) {
        float hc; int ha;
        if (pos < 10) { hc = s_c[warp][lane * 10 + pos]; ha = s_x[warp][lane * 10 + pos]; }
        else          { hc = 3.0e38f; ha = 0x7fffffff; }
        float bc = hc; int ba = ha; int bl = lane;
        #pragma unroll
        for (int o = 16; o > 0; o >>= 1) {
            float oc = __shfl_xor_sync(0xffffffffu, bc, o);
            int   oa = __shfl_xor_sync(0xffffffffu, ba, o);
            int   ol = __shfl_xor_sync(0xffffffffu, bl, o);
            if (oc < bc || (oc == bc && oa < ba)) { bc = oc; ba = oa; bl = ol; }
        }
        if (bc >= BIGC) break;
        if (lane == bl) pos++;
        if (lane == 0) {
            atomicOr(&g_mask[b * NA + ba], 1ull << m);
            s_win[warp][nsel] = ba;
        }
        nsel++;
    }
    if (lane == 0 && nsel > 0) {
        int base = atomicAdd(&g_cnt, nsel);
        for (int k = 0; k < nsel; k++)
            g_ent[base + k] = ((unsigned int)b << 20) | ((unsigned int)m << 14)
                            | (unsigned int)s_win[warp][k];
    }
}

// -------------------------------------------------------------------------
// Compact loss over matched entries; last block finalizes + resets run state.
__global__ void __launch_bounds__(256) klossC(const float* __restrict__ outp,
                                              const float* __restrict__ lab,
                                              float* __restrict__ out) {
    int idx = blockIdx.x * 256 + threadIdx.x;
    int cnt = g_cnt;
    float l_iou = 0.0f, l_obj = 0.0f, l_cls = 0.0f, nf = 0.0f;

    if (idx < NBLK) l_obj += g_pobj[idx];

    if (idx < cnt) {
        unsigned int e = g_ent[idx];
        int b = e >> 20;
        int m = (e >> 14) & 0x3f;
        int a = e & 0x3fff;
        unsigned long long mask = g_mask[b * NA + a];
        int first = __ffsll((long long)mask) - 1;
        if (m == first) {
            nf = 1.0f;
            int amg = __popcll(mask);
            const float* row = outp + ((size_t)b * NA + a) * NO;
            float obj = row[4];
            l_obj += -obj;

            int slot = g_slotOf[b * NA + a];
            int mgt;
            if (amg == 1) {
                mgt = first;
            } else {
                int ngt = g_ngt[b];
                float bv = 3.0e38f; mgt = 0;
                for (int mm = 0; mm < ngt; mm++) {
                    float c = g_cost[((size_t)b * NM + mm) * NA + slot];
                    if (c < bv) { bv = c; mgt = mm; }
                }
            }
            float pious = g_iou[((size_t)b * NM + mgt) * NA + slot];
            const float* lrow = lab + (b * NM + mgt) * 5;
            float gx = lrow[0], gy = lrow[1], gw = lrow[2], gh = lrow[3];
            int gc = (int)lrow[4];
            float cx = row[0], cy = row[1], w = row[2], h = row[3];
            float hw = 0.5f * gw, hh = 0.5f * gh, pw = 0.5f * w, ph = 0.5f * h;
            float tlx = fmaxf(gx - hw, cx - pw), brx = fminf(gx + hw, cx + pw);
            float tly = fmaxf(gy - hh, cy - ph), bry = fminf(gy + hh, cy + ph);
            float ai = ((tlx < brx) && (tly < bry)) ? (brx - tlx) * (bry - tly) : 0.0f;
            float iou = ai / (w * h + gw * gh - ai + 1e-16f);
            l_iou = 1.0f - iou * iou;

            float ssp = 0.0f;
            #pragma unroll 4
            for (int c = 0; c < NC; c++) {
                float x = row[5 + c];
                ssp += x + __logf(1.0f + __expf(-x));
            }
            l_cls = ssp - row[5 + gc] * pious;
        }
    }

    int lane = threadIdx.x & 31, wid = threadIdx.x >> 5;
    #pragma unroll
    for (int o = 16; o > 0; o >>= 1) {
        l_iou += __shfl_down_sync(0xffffffffu, l_iou, o);
        l_obj += __shfl_down_sync(0xffffffffu, l_obj, o);
        l_cls += __shfl_down_sync(0xffffffffu, l_cls, o);
        nf    += __shfl_down_sync(0xffffffffu, nf, o);
    }
    __shared__ float sred[8][4];
    if (lane == 0) {
        sred[wid][0] = l_iou; sred[wid][1] = l_obj;
        sred[wid][2] = l_cls; sred[wid][3] = nf;
    }
    __syncthreads();
    __shared__ bool isLast;
    if (threadIdx.x == 0) {
        float p0 = 0, p1 = 0, p2 = 0, p3 = 0;
        #pragma unroll
        for (int wq = 0; wq < 8; wq++) {
            p0 += sred[wq][0]; p1 += sred[wq][1];
            p2 += sred[wq][2]; p3 += sred[wq][3];
        }
        atomicAdd(&g_acc[0], (double)p0);
        atomicAdd(&g_acc[1], (double)p1);
        atomicAdd(&g_acc[2], (double)p2);
        atomicAdd(&g_acc[3], (double)p3);
        __threadfence();
        int v = atomicAdd(&g_done, 1);
        isLast = (v == LOSS_BLOCKS - 1);
    }
    __syncthreads();
    if (isLast && threadIdx.x == 0) {
        double nfg = g_acc[3];
        if (nfg < 1.0) nfg = 1.0;
        out[0] = (float)((5.0 * g_acc[0] + g_acc[1] + g_acc[2]) / nfg);
        // reset run state for the next graph replay
        g_acc[0] = 0.0; g_acc[1] = 0.0; g_acc[2] = 0.0; g_acc[3] = 0.0;
        g_cnt = 0; g_done = 0;
        #pragma unroll
        for (int bb = 0; bb < NB; bb++) g_nfg[bb] = 0;
    }
}

// -------------------------------------------------------------------------
extern "C" void kernel_launch(void* const* d_in, const int* in_sizes, int n_in,
                              void* d_out, int out_size) {
    const float* outp = (const float*)d_in[0];
    const float* xsh  = (const float*)d_in[1];
    const float* ysh  = (const float*)d_in[2];
    const float* est  = (const float*)d_in[3];
    const float* lab  = (const float*)d_in[4];
    (void)in_sizes; (void)n_in; (void)out_size;

    dim3 gA(GX, NB);
    kassignA<<<gA, 256>>>(outp, xsh, ysh, est, lab);

    kselect<<<(NB * NM + 3) / 4, 128>>>();

    klossC<<<LOSS_BLOCKS, 256>>>(outp, lab, (float*)d_out);
}

// round 7
// speedup vs baseline: 1.7076x; 1.7076x over previous
#include <cuda_runtime.h>
#include <cuda_bf16.h>

#define NB 32
#define NA 8400
#define NM 50
#define NC 80
#define NO 85
#define BIGC 1000000000.0f
#define GX 33
#define NBLK (GX * NB)
#define MAXENT 16384
#define LOSS_BLOCKS 64
#define ST 128                 // kselect threads

// ---- scratch ----
__device__ float g_cost[(size_t)NB * NM * NA];
__device__ float g_iou [(size_t)NB * NM * NA];
__device__ int   g_aidx[NB * NA];
__device__ int   g_slotOf[NB * NA];
__device__ unsigned long long g_mask[NB * NA];
__device__ float g_pobj[NBLK];
__device__ int g_ngt[NB];
__device__ int g_nfg[NB];              // zero-init; re-zeroed by klossC
__device__ unsigned int g_ent[MAXENT];
__device__ int g_cnt;
__device__ int g_done;
__device__ double g_acc[4];

// ---- FMA-pipe transcendentals ----
__device__ __forceinline__ float fexp(float x) {
    float t = x * 1.442695041f;
    float n = rintf(t);
    float g = fmaf(n, -0.6931471806f, t * 0.6931471806f);
    float p = 1.38888889e-3f;
    p = fmaf(p, g, 8.33333333e-3f);
    p = fmaf(p, g, 4.16666667e-2f);
    p = fmaf(p, g, 0.166666667f);
    p = fmaf(p, g, 0.5f);
    p = fmaf(p, g, 1.0f);
    p = fmaf(p, g, 1.0f);
    return p * __int_as_float(((int)n + 127) << 23);
}
__device__ __forceinline__ float flog(float x) {
    int xi = __float_as_int(x);
    int ei = ((xi >> 23) & 0xff) - 126;
    float m = __int_as_float((xi & 0x007fffff) | 0x3f000000);
    if (m < 0.70710678f) { m += m; ei -= 1; }
    float u = m - 1.0f;
    float z = u * u;
    float pp =  7.0376836292e-2f;
    pp = fmaf(pp, u, -1.1514610310e-1f);
    pp = fmaf(pp, u,  1.1676998740e-1f);
    pp = fmaf(pp, u, -1.2420140846e-1f);
    pp = fmaf(pp, u,  1.4249322787e-1f);
    pp = fmaf(pp, u, -1.6668057665e-1f);
    pp = fmaf(pp, u,  2.0000714765e-1f);
    pp = fmaf(pp, u, -2.4999993993e-1f);
    pp = fmaf(pp, u,  3.3333331174e-1f);
    float r = fmaf(pp * u, z, fmaf(-0.5f, z, u));
    return fmaf((float)ei, 0.69314718056f, r);
}
__device__ __forceinline__ float frsqrt(float x) {
    float r = __int_as_float(0x5f375a86 - (__float_as_int(x) >> 1));
    r = r * fmaf(-0.5f * x, r * r, 1.5f);
    r = r * fmaf(-0.5f * x, r * r, 1.5f);
    r = r * fmaf(-0.5f * x, r * r, 1.5f);
    return r;
}

// -------------------------------------------------------------------------
__global__ void __launch_bounds__(256) kassignA(
        const float* __restrict__ outp,
        const float* __restrict__ xsh,
        const float* __restrict__ ysh,
        const float* __restrict__ est,
        const float* __restrict__ lab) {
    int b = blockIdx.y;
    __shared__ float sl[NM * 5];
    __shared__ int s_nv;
    __shared__ int wcnt[8];
    __shared__ int bbase;
    for (int i = threadIdx.x; i < NM * 5; i += 256)
        sl[i] = lab[b * NM * 5 + i];
    __syncthreads();
    if (threadIdx.x == 0) {
        int n = 0;
        for (int m = 0; m < NM; m++) {
            float s = sl[m*5+0] + sl[m*5+1] + sl[m*5+2] + sl[m*5+3] + sl[m*5+4];
            if (s > 0.0f) n++;
        }
        s_nv = n;
        if (blockIdx.x == 0) g_ngt[b] = n;
    }
    __syncthreads();
    int nv = s_nv;

    int tid = threadIdx.x;
    int lane = tid & 31, wid = tid >> 5;
    int a = blockIdx.x * 256 + tid;
    bool act = (a < NA);
    float objbase = 0.0f;

    const float* row = outp + ((size_t)b * NA + a) * NO;
    bool fg = false;
    unsigned long long inboth = 0ull;

    if (act) {
        g_mask[b * NA + a] = 0ull;
        float stride = est[a];
        float xc = (xsh[a] + 0.5f) * stride;
        float yc = (ysh[a] + 0.5f) * stride;
        float rad = 2.5f * stride;
        float obj = row[4];
        objbase = fmaxf(obj, 0.0f) + __logf(1.0f + __expf(-fabsf(obj)));

        #pragma unroll 1
        for (int m = 0; m < nv; m++) {
            float gx = sl[m*5+0], gy = sl[m*5+1], gw = sl[m*5+2], gh = sl[m*5+3];
            float hw = 0.5f * gw, hh = 0.5f * gh;
            bool ib = (xc > gx - hw) && (gx + hw > xc) && (yc > gy - hh) && (gy + hh > yc);
            bool ic = (xc > gx - rad) && (xc < gx + rad) && (yc > gy - rad) && (yc < gy + rad);
            fg = fg || ib || ic;
            if (ib && ic) inboth |= 1ull << m;
        }
    }

    // block-level compaction of fg anchors
    unsigned wm = __ballot_sync(0xffffffffu, fg);
    if (lane == 0) wcnt[wid] = __popc(wm);
    __syncthreads();
    if (tid == 0) {
        int s = 0;
        #pragma unroll
        for (int w = 0; w < 8; w++) { int c = wcnt[w]; wcnt[w] = s; s += c; }
        bbase = (s > 0) ? atomicAdd(&g_nfg[b], s) : 0;
    }
    __syncthreads();
    int slot = bbase + wcnt[wid] + __popc(wm & ((1u << lane) - 1u));

    if (fg) {
        g_aidx[b * NA + slot] = a;
        g_slotOf[b * NA + a] = slot;

        float cx = row[0], cy = row[1], w = row[2], h = row[3], obj = row[4];
        float to = 1.0f + fexp(-obj);
        float q  = frsqrt(to);
        float lso = -0.5f * flog(to);

        float S = 0.0f;
        #pragma unroll 4
        for (int g = 0; g < NC; g += 5) {
            float prod = 1.0f;
            #pragma unroll
            for (int c = 0; c < 5; c++) {
                float x = row[5 + g + c];
                float t = 1.0f + fexp(-x);
                prod *= fmaf(-q, frsqrt(t), 1.0f);
            }
            S += flog(fmaxf(prod, 1e-30f));
        }

        float px1 = cx - 0.5f * w, px2 = cx + 0.5f * w;
        float py1 = cy - 0.5f * h, py2 = cy + 0.5f * h;
        float area_p = w * h;
        #pragma unroll 1
        for (int m = 0; m < nv; m++) {
            size_t off = ((size_t)b * NM + m) * NA + slot;
            float gx = sl[m*5+0], gy = sl[m*5+1], gw = sl[m*5+2], gh = sl[m*5+3];
            float hw = 0.5f * gw, hh = 0.5f * gh;
            float tlx = fmaxf(gx - hw, px1), brx = fminf(gx + hw, px2);
            float tly = fmaxf(gy - hh, py1), bry = fminf(gy + hh, py2);
            float ai = ((tlx < brx) && (tly < bry)) ? (brx - tlx) * (bry - tly) : 0.0f;
            float iouv = ai / (gw * gh + area_p - ai + 1e-16f);
            int c = (int)sl[m*5+4];
            float x = row[5 + c];
            float t = 1.0f + __expf(-x);
            float lg = __logf(t);
            float p = q * __frsqrt_rn(t);
            float lp  = fmaxf(lso - 0.5f * lg, -100.0f);
            float l1p = fmaxf(__logf(1.0f - p), -100.0f);
            float cls_cost = -(lp + S - l1p);
            float extra = ((inboth >> m) & 1ull) ? 0.0f : 100000.0f;
            float cost = cls_cost - 3.0f * __logf(iouv + 1e-8f) + extra;
            g_iou[off] = iouv;
            g_cost[off] = cost;
        }
    }

    #pragma unroll
    for (int o = 16; o > 0; o >>= 1)
        objbase += __shfl_down_sync(0xffffffffu, objbase, o);
    __shared__ float sred[8];
    if (lane == 0) sred[wid] = objbase;
    __syncthreads();
    if (tid == 0) {
        float p = 0;
        #pragma unroll
        for (int wq = 0; wq < 8; wq++) p += sred[wq];
        g_pobj[blockIdx.y * GX + blockIdx.x] = p;
    }
}

// -------------------------------------------------------------------------
// Block per (b,m): scan compacted columns -> sorted 10-lists -> merge tree.
__global__ void __launch_bounds__(ST) kselect() {
    int m = blockIdx.x, b = blockIdx.y;
    if (m >= g_ngt[b]) return;

    int n = g_nfg[b];
    size_t rowbase = ((size_t)b * NM + m) * NA;
    const float* iour  = g_iou  + rowbase;
    const float* costr = g_cost + rowbase;
    const int*   aidxr = g_aidx + b * NA;
    int t = threadIdx.x;

    float ti[10], tc[10];
    int   tx[10];
    #pragma unroll
    for (int k = 0; k < 10; k++) { ti[k] = 0.0f; tc[k] = 3.0e38f; tx[k] = 0x7fffffff; }

    for (int i = t; i < n; i += ST) {
        float v = iour[i];
        float c = costr[i];
        if (v > ti[9]) {
            float cur = v;
            #pragma unroll
            for (int k = 0; k < 10; k++)
                if (cur > ti[k]) { float tmp = ti[k]; ti[k] = cur; cur = tmp; }
        }
        if (c < tc[9]) {
            int ci = aidxr[i];
            float cv = c;
            #pragma unroll
            for (int k = 0; k < 10; k++) {
                bool sw = (cv < tc[k]) || (cv == tc[k] && ci < tx[k]);
                if (sw) {
                    float tf = tc[k]; tc[k] = cv; cv = tf;
                    int   tn = tx[k]; tx[k] = ci; ci = tn;
                }
            }
        }
    }

    __shared__ float s_v[ST * 10];
    __shared__ float s_c[ST * 10];
    __shared__ int   s_x[ST * 10];
    #pragma unroll
    for (int k = 0; k < 10; k++) {
        s_v[t * 10 + k] = ti[k];
        s_c[t * 10 + k] = tc[k];
        s_x[t * 10 + k] = tx[k];
    }
    __syncthreads();

    for (int stride = 1; stride < ST; stride <<= 1) {
        if ((t & (2 * stride - 1)) == 0) {
            int A = t * 10, B = (t + stride) * 10;
            {
                float M[10]; int i = 0, j = 0;
                #pragma unroll
                for (int k = 0; k < 10; k++) {
                    float av = s_v[A + i], bv = s_v[B + j];
                    if (av >= bv) { M[k] = av; i++; } else { M[k] = bv; j++; }
                }
                #pragma unroll
                for (int k = 0; k < 10; k++) s_v[A + k] = M[k];
            }
            {
                float Mc[10]; int Mx[10]; int i = 0, j = 0;
                #pragma unroll
                for (int k = 0; k < 10; k++) {
                    float ac = s_c[A + i], bc = s_c[B + j];
                    int   ax = s_x[A + i], bx = s_x[B + j];
                    bool takeA = (ac < bc) || (ac == bc && ax < bx);
                    if (takeA) { Mc[k] = ac; Mx[k] = ax; i++; }
                    else       { Mc[k] = bc; Mx[k] = bx; j++; }
                }
                #pragma unroll
                for (int k = 0; k < 10; k++) { s_c[A + k] = Mc[k]; s_x[A + k] = Mx[k]; }
            }
        }
        __syncthreads();
    }

    if (t == 0) {
        float ksum = 0.0f;
        #pragma unroll
        for (int k = 0; k < 10; k++) ksum += s_v[k];
        int dynk = (int)ksum;
        if (dynk < 1) dynk = 1;
        if (dynk > 10) dynk = 10;

        unsigned int ents[10];
        int ns = 0;
        for (int k = 0; k < dynk; k++) {
            if (s_c[k] >= BIGC) break;
            int a = s_x[k];
            atomicOr(&g_mask[b * NA + a], 1ull << m);
            ents[ns++] = ((unsigned int)b << 20) | ((unsigned int)m << 14) | (unsigned int)a;
        }
        if (ns > 0) {
            int base = atomicAdd(&g_cnt, ns);
            for (int k = 0; k < ns; k++) g_ent[base + k] = ents[k];
        }
    }
}

// -------------------------------------------------------------------------
__global__ void __launch_bounds__(256) klossC(const float* __restrict__ outp,
                                              const float* __restrict__ lab,
                                              float* __restrict__ out) {
    int idx = blockIdx.x * 256 + threadIdx.x;
    int cnt = g_cnt;
    float l_iou = 0.0f, l_obj = 0.0f, l_cls = 0.0f, nf = 0.0f;

    if (idx < NBLK) l_obj += g_pobj[idx];

    if (idx < cnt) {
        unsigned int e = g_ent[idx];
        int b = e >> 20;
        int m = (e >> 14) & 0x3f;
        int a = e & 0x3fff;
        unsigned long long mask = g_mask[b * NA + a];
        int first = __ffsll((long long)mask) - 1;
        if (m == first) {
            nf = 1.0f;
            int amg = __popcll(mask);
            const float* row = outp + ((size_t)b * NA + a) * NO;
            float obj = row[4];
            l_obj += -obj;

            int slot = g_slotOf[b * NA + a];
            int mgt;
            if (amg == 1) {
                mgt = first;
            } else {
                int ngt = g_ngt[b];
                float bv = 3.0e38f; mgt = 0;
                for (int mm = 0; mm < ngt; mm++) {
                    float c = g_cost[((size_t)b * NM + mm) * NA + slot];
                    if (c < bv) { bv = c; mgt = mm; }
                }
            }
            float pious = g_iou[((size_t)b * NM + mgt) * NA + slot];
            const float* lrow = lab + (b * NM + mgt) * 5;
            float gx = lrow[0], gy = lrow[1], gw = lrow[2], gh = lrow[3];
            int gc = (int)lrow[4];
            float cx = row[0], cy = row[1], w = row[2], h = row[3];
            float hw = 0.5f * gw, hh = 0.5f * gh, pw = 0.5f * w, ph = 0.5f * h;
            float tlx = fmaxf(gx - hw, cx - pw), brx = fminf(gx + hw, cx + pw);
            float tly = fmaxf(gy - hh, cy - ph), bry = fminf(gy + hh, cy + ph);
            float ai = ((tlx < brx) && (tly < bry)) ? (brx - tlx) * (bry - tly) : 0.0f;
            float iou = ai / (w * h + gw * gh - ai + 1e-16f);
            l_iou = 1.0f - iou * iou;

            float ssp = 0.0f;
            #pragma unroll 4
            for (int c = 0; c < NC; c++) {
                float x = row[5 + c];
                ssp += x + __logf(1.0f + __expf(-x));
            }
            l_cls = ssp - row[5 + gc] * pious;
        }
    }

    int lane = threadIdx.x & 31, wid = threadIdx.x >> 5;
    #pragma unroll
    for (int o = 16; o > 0; o >>= 1) {
        l_iou += __shfl_down_sync(0xffffffffu, l_iou, o);
        l_obj += __shfl_down_sync(0xffffffffu, l_obj, o);
        l_cls += __shfl_down_sync(0xffffffffu, l_cls, o);
        nf    += __shfl_down_sync(0xffffffffu, nf, o);
    }
    __shared__ float sred[8][4];
    if (lane == 0) {
        sred[wid][0] = l_iou; sred[wid][1] = l_obj;
        sred[wid][2] = l_cls; sred[wid][3] = nf;
    }
    __syncthreads();
    __shared__ bool isLast;
    if (threadIdx.x == 0) {
        float p0 = 0, p1 = 0, p2 = 0, p3 = 0;
        #pragma unroll
        for (int wq = 0; wq < 8; wq++) {
            p0 += sred[wq][0]; p1 += sred[wq][1];
            p2 += sred[wq][2]; p3 += sred[wq][3];
        }
        atomicAdd(&g_acc[0], (double)p0);
        atomicAdd(&g_acc[1], (double)p1);
        atomicAdd(&g_acc[2], (double)p2);
        atomicAdd(&g_acc[3], (double)p3);
        __threadfence();
        int v = atomicAdd(&g_done, 1);
        isLast = (v == LOSS_BLOCKS - 1);
    }
    __syncthreads();
    if (isLast && threadIdx.x == 0) {
        double nfg = g_acc[3];
        if (nfg < 1.0) nfg = 1.0;
        out[0] = (float)((5.0 * g_acc[0] + g_acc[1] + g_acc[2]) / nfg);
        g_acc[0] = 0.0; g_acc[1] = 0.0; g_acc[2] = 0.0; g_acc[3] = 0.0;
        g_cnt = 0; g_done = 0;
        #pragma unroll
        for (int bb = 0; bb < NB; bb++) g_nfg[bb] = 0;
    }
}

// -------------------------------------------------------------------------
extern "C" void kernel_launch(void* const* d_in, const int* in_sizes, int n_in,
                              void* d_out, int out_size) {
    const float* outp = (const float*)d_in[0];
    const float* xsh  = (const float*)d_in[1];
    const float* ysh  = (const float*)d_in[2];
    const float* est  = (const float*)d_in[3];
    const float* lab  = (const float*)d_in[4];
    (void)in_sizes; (void)n_in; (void)out_size;

    dim3 gA(GX, NB);
    kassignA<<<gA, 256>>>(outp, xsh, ysh, est, lab);

    dim3 gB(NM, NB);
    kselect<<<gB, ST>>>();

    klossC<<<LOSS_BLOCKS, 256>>>(outp, lab, (float*)d_out);
}

// round 8
// speedup vs baseline: 1.8938x; 1.1091x over previous
#include <cuda_runtime.h>
#include <cuda_bf16.h>

#define NB 32
#define NA 8400
#define NM 50
#define NC 80
#define NO 85
#define BIGC 1000000000.0f
#define GX 33
#define NBLK (GX * NB)
#define MAXENT 16384
#define LOSS_BLOCKS 64
#define ST 128                 // kselect threads

// ---- scratch ----
__device__ float g_cost[(size_t)NB * NM * NA];
__device__ float g_iou [(size_t)NB * NM * NA];
__device__ int   g_aidx[NB * NA];
__device__ int   g_slotOf[NB * NA];
__device__ unsigned long long g_mask[NB * NA];
__device__ float g_pobj[NBLK];
__device__ int g_ngt[NB];
__device__ int g_nfg[NB];              // zero-init; re-zeroed by klossC
__device__ unsigned int g_ent[MAXENT];
__device__ int g_cnt;
__device__ int g_done;
__device__ double g_acc[4];

// ---- FMA-pipe transcendentals ----
__device__ __forceinline__ float fexp(float x) {
    float t = x * 1.442695041f;
    float n = rintf(t);
    float g = fmaf(n, -0.6931471806f, t * 0.6931471806f);
    float p = 8.33333333e-3f;
    p = fmaf(p, g, 4.16666667e-2f);
    p = fmaf(p, g, 0.166666667f);
    p = fmaf(p, g, 0.5f);
    p = fmaf(p, g, 1.0f);
    p = fmaf(p, g, 1.0f);
    return p * __int_as_float(((int)n + 127) << 23);
}
__device__ __forceinline__ float flog(float x) {
    int xi = __float_as_int(x);
    int ei = ((xi >> 23) & 0xff) - 126;
    float m = __int_as_float((xi & 0x007fffff) | 0x3f000000);
    if (m < 0.70710678f) { m += m; ei -= 1; }
    float u = m - 1.0f;
    float z = u * u;
    float pp =  7.0376836292e-2f;
    pp = fmaf(pp, u, -1.1514610310e-1f);
    pp = fmaf(pp, u,  1.1676998740e-1f);
    pp = fmaf(pp, u, -1.2420140846e-1f);
    pp = fmaf(pp, u,  1.4249322787e-1f);
    pp = fmaf(pp, u, -1.6668057665e-1f);
    pp = fmaf(pp, u,  2.0000714765e-1f);
    pp = fmaf(pp, u, -2.4999993993e-1f);
    pp = fmaf(pp, u,  3.3333331174e-1f);
    float r = fmaf(pp * u, z, fmaf(-0.5f, z, u));
    return fmaf((float)ei, 0.69314718056f, r);
}
__device__ __forceinline__ float frsqrt(float x) {
    float r = __int_as_float(0x5f375a86 - (__float_as_int(x) >> 1));
    r = r * fmaf(-0.5f * x, r * r, 1.5f);
    r = r * fmaf(-0.5f * x, r * r, 1.5f);
    return r;
}

// -------------------------------------------------------------------------
__global__ void __launch_bounds__(256) kassignA(
        const float* __restrict__ outp,
        const float* __restrict__ xsh,
        const float* __restrict__ ysh,
        const float* __restrict__ est,
        const float* __restrict__ lab) {
    int b = blockIdx.y;
    int a0 = blockIdx.x * 256;
    __shared__ float sl[NM * 5];
    __shared__ int s_nv;
    __shared__ int wcnt[8];
    __shared__ int bbase, s_cnt;
    __shared__ unsigned long long s_inb[256];
    __shared__ short s_lt[256];
    for (int i = threadIdx.x; i < NM * 5; i += 256)
        sl[i] = lab[b * NM * 5 + i];
    __syncthreads();
    if (threadIdx.x == 0) {
        int n = 0;
        for (int m = 0; m < NM; m++) {
            float s = sl[m*5+0] + sl[m*5+1] + sl[m*5+2] + sl[m*5+3] + sl[m*5+4];
            if (s > 0.0f) n++;
        }
        s_nv = n;
        if (blockIdx.x == 0) g_ngt[b] = n;
    }
    __syncthreads();
    int nv = s_nv;

    int tid = threadIdx.x;
    int lane = tid & 31, wid = tid >> 5;
    int a = a0 + tid;
    bool act = (a < NA);
    float objbase = 0.0f;

    bool fg = false;
    unsigned long long inboth = 0ull;

    if (act) {
        g_mask[b * NA + a] = 0ull;
        float stride = est[a];
        float xc = (xsh[a] + 0.5f) * stride;
        float yc = (ysh[a] + 0.5f) * stride;
        float rad = 2.5f * stride;
        float obj = outp[((size_t)b * NA + a) * NO + 4];
        objbase = fmaxf(obj, 0.0f) + __logf(1.0f + __expf(-fabsf(obj)));

        #pragma unroll 1
        for (int m = 0; m < nv; m++) {
            float gx = sl[m*5+0], gy = sl[m*5+1], gw = sl[m*5+2], gh = sl[m*5+3];
            float hw = 0.5f * gw, hh = 0.5f * gh;
            bool ib = (xc > gx - hw) && (gx + hw > xc) && (yc > gy - hh) && (gy + hh > yc);
            bool ic = (xc > gx - rad) && (xc < gx + rad) && (yc > gy - rad) && (yc < gy + rad);
            fg = fg || ib || ic;
            if (ib && ic) inboth |= 1ull << m;
        }
    }

    // ---- block-level compaction of fg anchors ----
    unsigned wm = __ballot_sync(0xffffffffu, fg);
    if (lane == 0) wcnt[wid] = __popc(wm);
    __syncthreads();
    if (tid == 0) {
        int s = 0;
        #pragma unroll
        for (int w = 0; w < 8; w++) { int c = wcnt[w]; wcnt[w] = s; s += c; }
        s_cnt = s;
        bbase = (s > 0) ? atomicAdd(&g_nfg[b], s) : 0;
    }
    __syncthreads();
    int rank = wcnt[wid] + __popc(wm & ((1u << lane) - 1u));

    if (fg) {
        int slot = bbase + rank;
        g_aidx[b * NA + slot] = a;
        g_slotOf[b * NA + a] = slot;
        s_lt[rank] = (short)tid;
        s_inb[rank] = inboth;
    }
    __syncthreads();

    // ---- dense heavy phase: thread t handles block-local fg anchor t ----
    int cnt = s_cnt;
    if (tid < cnt) {
        int lt = s_lt[tid];
        int slot = bbase + tid;
        unsigned long long inb = s_inb[tid];
        const float* row = outp + ((size_t)b * NA + a0 + lt) * NO;

        float cx = row[0], cy = row[1], w = row[2], h = row[3], obj = row[4];
        float to = 1.0f + fexp(-obj);
        float q  = frsqrt(to);          // sqrt(sigmoid(obj))
        float lso = -0.5f * flog(to);

        float S = 0.0f;
        #pragma unroll 4
        for (int g = 0; g < NC; g += 5) {
            float prod = 1.0f;
            #pragma unroll
            for (int c = 0; c < 5; c++) {
                float x = row[5 + g + c];
                float t = 1.0f + fexp(-x);
                prod *= fmaf(-q, frsqrt(t), 1.0f);
            }
            S += flog(fmaxf(prod, 1e-30f));
        }

        float px1 = cx - 0.5f * w, px2 = cx + 0.5f * w;
        float py1 = cy - 0.5f * h, py2 = cy + 0.5f * h;
        float area_p = w * h;
        #pragma unroll 1
        for (int m = 0; m < nv; m++) {
            size_t off = ((size_t)b * NM + m) * NA + slot;
            float gx = sl[m*5+0], gy = sl[m*5+1], gw = sl[m*5+2], gh = sl[m*5+3];
            float hw = 0.5f * gw, hh = 0.5f * gh;
            float tlx = fmaxf(gx - hw, px1), brx = fminf(gx + hw, px2);
            float tly = fmaxf(gy - hh, py1), bry = fminf(gy + hh, py2);
            float ai = ((tlx < brx) && (tly < bry)) ? (brx - tlx) * (bry - tly) : 0.0f;
            float iouv = ai / (gw * gh + area_p - ai + 1e-16f);
            int c = (int)sl[m*5+4];
            float x = row[5 + c];
            float t = 1.0f + __expf(-x);
            float lg = __logf(t);
            float p = q * __frsqrt_rn(t);
            float lp  = fmaxf(lso - 0.5f * lg, -100.0f);
            float l1p = fmaxf(__logf(1.0f - p), -100.0f);
            float cls_cost = -(lp + S - l1p);
            float extra = ((inb >> m) & 1ull) ? 0.0f : 100000.0f;
            float cost = cls_cost - 3.0f * __logf(iouv + 1e-8f) + extra;
            g_iou[off] = iouv;
            g_cost[off] = cost;
        }
    }

    #pragma unroll
    for (int o = 16; o > 0; o >>= 1)
        objbase += __shfl_down_sync(0xffffffffu, objbase, o);
    __shared__ float sred[8];
    if (lane == 0) sred[wid] = objbase;
    __syncthreads();
    if (tid == 0) {
        float p = 0;
        #pragma unroll
        for (int wq = 0; wq < 8; wq++) p += sred[wq];
        g_pobj[blockIdx.y * GX + blockIdx.x] = p;
    }
}

// -------------------------------------------------------------------------
// Block per (b,m): scan compacted columns -> sorted 10-lists -> merge tree.
__global__ void __launch_bounds__(ST) kselect() {
    int m = blockIdx.x, b = blockIdx.y;
    if (m >= g_ngt[b]) return;

    int n = g_nfg[b];
    size_t rowbase = ((size_t)b * NM + m) * NA;
    const float* iour  = g_iou  + rowbase;
    const float* costr = g_cost + rowbase;
    const int*   aidxr = g_aidx + b * NA;
    int t = threadIdx.x;

    float ti[10], tc[10];
    int   tx[10];
    #pragma unroll
    for (int k = 0; k < 10; k++) { ti[k] = 0.0f; tc[k] = 3.0e38f; tx[k] = 0x7fffffff; }

    for (int i = t; i < n; i += ST) {
        float v = iour[i];
        float c = costr[i];
        if (v > ti[9]) {
            float cur = v;
            #pragma unroll
            for (int k = 0; k < 10; k++)
                if (cur > ti[k]) { float tmp = ti[k]; ti[k] = cur; cur = tmp; }
        }
        if (c < tc[9]) {
            int ci = aidxr[i];
            float cv = c;
            #pragma unroll
            for (int k = 0; k < 10; k++) {
                bool sw = (cv < tc[k]) || (cv == tc[k] && ci < tx[k]);
                if (sw) {
                    float tf = tc[k]; tc[k] = cv; cv = tf;
                    int   tn = tx[k]; tx[k] = ci; ci = tn;
                }
            }
        }
    }

    __shared__ float s_v[ST * 10];
    __shared__ float s_c[ST * 10];
    __shared__ int   s_x[ST * 10];
    #pragma unroll
    for (int k = 0; k < 10; k++) {
        s_v[t * 10 + k] = ti[k];
        s_c[t * 10 + k] = tc[k];
        s_x[t * 10 + k] = tx[k];
    }
    __syncthreads();

    for (int stride = 1; stride < ST; stride <<= 1) {
        if ((t & (2 * stride - 1)) == 0) {
            int A = t * 10, B = (t + stride) * 10;
            {
                float M[10]; int i = 0, j = 0;
                #pragma unroll
                for (int k = 0; k < 10; k++) {
                    float av = s_v[A + i], bv = s_v[B + j];
                    if (av >= bv) { M[k] = av; i++; } else { M[k] = bv; j++; }
                }
                #pragma unroll
                for (int k = 0; k < 10; k++) s_v[A + k] = M[k];
            }
            {
                float Mc[10]; int Mx[10]; int i = 0, j = 0;
                #pragma unroll
                for (int k = 0; k < 10; k++) {
                    float ac = s_c[A + i], bc = s_c[B + j];
                    int   ax = s_x[A + i], bx = s_x[B + j];
                    bool takeA = (ac < bc) || (ac == bc && ax < bx);
                    if (takeA) { Mc[k] = ac; Mx[k] = ax; i++; }
                    else       { Mc[k] = bc; Mx[k] = bx; j++; }
                }
                #pragma unroll
                for (int k = 0; k < 10; k++) { s_c[A + k] = Mc[k]; s_x[A + k] = Mx[k]; }
            }
        }
        __syncthreads();
    }

    if (t == 0) {
        float ksum = 0.0f;
        #pragma unroll
        for (int k = 0; k < 10; k++) ksum += s_v[k];
        int dynk = (int)ksum;
        if (dynk < 1) dynk = 1;
        if (dynk > 10) dynk = 10;

        unsigned int ents[10];
        int ns = 0;
        for (int k = 0; k < dynk; k++) {
            if (s_c[k] >= BIGC) break;
            int a = s_x[k];
            atomicOr(&g_mask[b * NA + a], 1ull << m);
            ents[ns++] = ((unsigned int)b << 20) | ((unsigned int)m << 14) | (unsigned int)a;
        }
        if (ns > 0) {
            int base = atomicAdd(&g_cnt, ns);
            for (int k = 0; k < ns; k++) g_ent[base + k] = ents[k];
        }
    }
}

// -------------------------------------------------------------------------
__global__ void __launch_bounds__(256) klossC(const float* __restrict__ outp,
                                              const float* __restrict__ lab,
                                              float* __restrict__ out) {
    int idx = blockIdx.x * 256 + threadIdx.x;
    int cnt = g_cnt;
    float l_iou = 0.0f, l_obj = 0.0f, l_cls = 0.0f, nf = 0.0f;

    if (idx < NBLK) l_obj += g_pobj[idx];

    if (idx < cnt) {
        unsigned int e = g_ent[idx];
        int b = e >> 20;
        int m = (e >> 14) & 0x3f;
        int a = e & 0x3fff;
        unsigned long long mask = g_mask[b * NA + a];
        int first = __ffsll((long long)mask) - 1;
        if (m == first) {
            nf = 1.0f;
            int amg = __popcll(mask);
            const float* row = outp + ((size_t)b * NA + a) * NO;
            float obj = row[4];
            l_obj += -obj;

            int slot = g_slotOf[b * NA + a];
            int mgt;
            if (amg == 1) {
                mgt = first;
            } else {
                int ngt = g_ngt[b];
                float bv = 3.0e38f; mgt = 0;
                for (int mm = 0; mm < ngt; mm++) {
                    float c = g_cost[((size_t)b * NM + mm) * NA + slot];
                    if (c < bv) { bv = c; mgt = mm; }
                }
            }
            float pious = g_iou[((size_t)b * NM + mgt) * NA + slot];
            const float* lrow = lab + (b * NM + mgt) * 5;
            float gx = lrow[0], gy = lrow[1], gw = lrow[2], gh = lrow[3];
            int gc = (int)lrow[4];
            float cx = row[0], cy = row[1], w = row[2], h = row[3];
            float hw = 0.5f * gw, hh = 0.5f * gh, pw = 0.5f * w, ph = 0.5f * h;
            float tlx = fmaxf(gx - hw, cx - pw), brx = fminf(gx + hw, cx + pw);
            float tly = fmaxf(gy - hh, cy - ph), bry = fminf(gy + hh, cy + ph);
            float ai = ((tlx < brx) && (tly < bry)) ? (brx - tlx) * (bry - tly) : 0.0f;
            float iou = ai / (w * h + gw * gh - ai + 1e-16f);
            l_iou = 1.0f - iou * iou;

            float ssp = 0.0f;
            #pragma unroll 4
            for (int c = 0; c < NC; c++) {
                float x = row[5 + c];
                ssp += x + __logf(1.0f + __expf(-x));
            }
            l_cls = ssp - row[5 + gc] * pious;
        }
    }

    int lane = threadIdx.x & 31, wid = threadIdx.x >> 5;
    #pragma unroll
    for (int o = 16; o > 0; o >>= 1) {
        l_iou += __shfl_down_sync(0xffffffffu, l_iou, o);
        l_obj += __shfl_down_sync(0xffffffffu, l_obj, o);
        l_cls += __shfl_down_sync(0xffffffffu, l_cls, o);
        nf    += __shfl_down_sync(0xffffffffu, nf, o);
    }
    __shared__ float sred[8][4];
    if (lane == 0) {
        sred[wid][0] = l_iou; sred[wid][1] = l_obj;
        sred[wid][2] = l_cls; sred[wid][3] = nf;
    }
    __syncthreads();
    __shared__ bool isLast;
    if (threadIdx.x == 0) {
        float p0 = 0, p1 = 0, p2 = 0, p3 = 0;
        #pragma unroll
        for (int wq = 0; wq < 8; wq++) {
            p0 += sred[wq][0]; p1 += sred[wq][1];
            p2 += sred[wq][2]; p3 += sred[wq][3];
        }
        atomicAdd(&g_acc[0], (double)p0);
        atomicAdd(&g_acc[1], (double)p1);
        atomicAdd(&g_acc[2], (double)p2);
        atomicAdd(&g_acc[3], (double)p3);
        __threadfence();
        int v = atomicAdd(&g_done, 1);
        isLast = (v == LOSS_BLOCKS - 1);
    }
    __syncthreads();
    if (isLast && threadIdx.x == 0) {
        double nfg = g_acc[3];
        if (nfg < 1.0) nfg = 1.0;
        out[0] = (float)((5.0 * g_acc[0] + g_acc[1] + g_acc[2]) / nfg);
        g_acc[0] = 0.0; g_acc[1] = 0.0; g_acc[2] = 0.0; g_acc[3] = 0.0;
        g_cnt = 0; g_done = 0;
        #pragma unroll
        for (int bb = 0; bb < NB; bb++) g_nfg[bb] = 0;
    }
}

// -------------------------------------------------------------------------
extern "C" void kernel_launch(void* const* d_in, const int* in_sizes, int n_in,
                              void* d_out, int out_size) {
    const float* outp = (const float*)d_in[0];
    const float* xsh  = (const float*)d_in[1];
    const float* ysh  = (const float*)d_in[2];
    const float* est  = (const float*)d_in[3];
    const float* lab  = (const float*)d_in[4];
    (void)in_sizes; (void)n_in; (void)out_size;

    dim3 gA(GX, NB);
    kassignA<<<gA, 256>>>(outp, xsh, ysh, est, lab);

    dim3 gB(NM, NB);
    kselect<<<gB, ST>>>();

    klossC<<<LOSS_BLOCKS, 256>>>(outp, lab, (float*)d_out);
}

// round 9
// speedup vs baseline: 1.9182x; 1.0129x over previous
#include <cuda_runtime.h>
#include <cuda_bf16.h>

#define NB 32
#define NA 8400
#define NM 50
#define NC 80
#define NO 85
#define BIGC 1000000000.0f
#define GX 33
#define NBLK (GX * NB)
#define MAXENT 16384
#define LOSS_BLOCKS 64
#define ST 256                 // kselect threads

// ---- scratch ----
__device__ float g_cost[(size_t)NB * NM * NA];
__device__ float g_iou [(size_t)NB * NM * NA];
__device__ int   g_aidx[NB * NA];
__device__ unsigned long long g_inb[NB * NA];   // per-slot inboth mask
__device__ int   g_slotOf[NB * NA];
__device__ unsigned long long g_mask[NB * NA];
__device__ float g_pobj[NBLK];
__device__ int g_ngt[NB];
__device__ int g_nfg[NB];              // zero-init; re-zeroed by klossC
__device__ unsigned int g_ent[MAXENT];
__device__ int g_cnt;
__device__ int g_done;
__device__ double g_acc[4];

// ---- FMA-pipe transcendentals ----
__device__ __forceinline__ float fexp(float x) {
    float t = x * 1.442695041f;
    float n = rintf(t);
    float g = fmaf(n, -0.6931471806f, t * 0.6931471806f);
    float p = 8.33333333e-3f;
    p = fmaf(p, g, 4.16666667e-2f);
    p = fmaf(p, g, 0.166666667f);
    p = fmaf(p, g, 0.5f);
    p = fmaf(p, g, 1.0f);
    p = fmaf(p, g, 1.0f);
    return p * __int_as_float(((int)n + 127) << 23);
}
__device__ __forceinline__ float flog(float x) {
    int xi = __float_as_int(x);
    int ei = ((xi >> 23) & 0xff) - 126;
    float m = __int_as_float((xi & 0x007fffff) | 0x3f000000);
    if (m < 0.70710678f) { m += m; ei -= 1; }
    float u = m - 1.0f;
    float z = u * u;
    float pp =  7.0376836292e-2f;
    pp = fmaf(pp, u, -1.1514610310e-1f);
    pp = fmaf(pp, u,  1.1676998740e-1f);
    pp = fmaf(pp, u, -1.2420140846e-1f);
    pp = fmaf(pp, u,  1.4249322787e-1f);
    pp = fmaf(pp, u, -1.6668057665e-1f);
    pp = fmaf(pp, u,  2.0000714765e-1f);
    pp = fmaf(pp, u, -2.4999993993e-1f);
    pp = fmaf(pp, u,  3.3333331174e-1f);
    float r = fmaf(pp * u, z, fmaf(-0.5f, z, u));
    return fmaf((float)ei, 0.69314718056f, r);
}
__device__ __forceinline__ float frsqrt(float x) {
    float r = __int_as_float(0x5f375a86 - (__float_as_int(x) >> 1));
    r = r * fmaf(-0.5f * x, r * r, 1.5f);
    r = r * fmaf(-0.5f * x, r * r, 1.5f);
    return r;
}

// -------------------------------------------------------------------------
// Phase 1: geometry, fg, compaction, objbase. Uniform light work.
__global__ void __launch_bounds__(256) kassignA(
        const float* __restrict__ outp,
        const float* __restrict__ xsh,
        const float* __restrict__ ysh,
        const float* __restrict__ est,
        const float* __restrict__ lab) {
    int b = blockIdx.y;
    __shared__ float sl[NM * 5];
    __shared__ int s_nv;
    __shared__ int wcnt[8];
    __shared__ int bbase;
    for (int i = threadIdx.x; i < NM * 5; i += 256)
        sl[i] = lab[b * NM * 5 + i];
    __syncthreads();
    if (threadIdx.x == 0) {
        int n = 0;
        for (int m = 0; m < NM; m++) {
            float s = sl[m*5+0] + sl[m*5+1] + sl[m*5+2] + sl[m*5+3] + sl[m*5+4];
            if (s > 0.0f) n++;
        }
        s_nv = n;
        if (blockIdx.x == 0) g_ngt[b] = n;
    }
    __syncthreads();
    int nv = s_nv;

    int tid = threadIdx.x;
    int lane = tid & 31, wid = tid >> 5;
    int a = blockIdx.x * 256 + tid;
    bool act = (a < NA);
    float objbase = 0.0f;

    bool fg = false;
    unsigned long long inboth = 0ull;

    if (act) {
        g_mask[b * NA + a] = 0ull;
        float stride = est[a];
        float xc = (xsh[a] + 0.5f) * stride;
        float yc = (ysh[a] + 0.5f) * stride;
        float rad = 2.5f * stride;
        float obj = outp[((size_t)b * NA + a) * NO + 4];
        objbase = fmaxf(obj, 0.0f) + __logf(1.0f + __expf(-fabsf(obj)));

        #pragma unroll 1
        for (int m = 0; m < nv; m++) {
            float gx = sl[m*5+0], gy = sl[m*5+1], gw = sl[m*5+2], gh = sl[m*5+3];
            float hw = 0.5f * gw, hh = 0.5f * gh;
            bool ib = (xc > gx - hw) && (gx + hw > xc) && (yc > gy - hh) && (gy + hh > yc);
            bool ic = (xc > gx - rad) && (xc < gx + rad) && (yc > gy - rad) && (yc < gy + rad);
            fg = fg || ib || ic;
            if (ib && ic) inboth |= 1ull << m;
        }
    }

    unsigned wm = __ballot_sync(0xffffffffu, fg);
    if (lane == 0) wcnt[wid] = __popc(wm);
    __syncthreads();
    if (tid == 0) {
        int s = 0;
        #pragma unroll
        for (int w = 0; w < 8; w++) { int c = wcnt[w]; wcnt[w] = s; s += c; }
        bbase = (s > 0) ? atomicAdd(&g_nfg[b], s) : 0;
    }
    __syncthreads();
    int rank = wcnt[wid] + __popc(wm & ((1u << lane) - 1u));

    if (fg) {
        int slot = bbase + rank;
        g_aidx[b * NA + slot] = a;
        g_inb[b * NA + slot] = inboth;
        g_slotOf[b * NA + a] = slot;
    }

    #pragma unroll
    for (int o = 16; o > 0; o >>= 1)
        objbase += __shfl_down_sync(0xffffffffu, objbase, o);
    __shared__ float sred[8];
    if (lane == 0) sred[wid] = objbase;
    __syncthreads();
    if (tid == 0) {
        float p = 0;
        #pragma unroll
        for (int wq = 0; wq < 8; wq++) p += sred[wq];
        g_pobj[blockIdx.y * GX + blockIdx.x] = p;
    }
}

// -------------------------------------------------------------------------
// Phase 2: heavy per-fg-anchor work over the compacted slot space. Uniform.
__global__ void __launch_bounds__(256) kheavy(
        const float* __restrict__ outp,
        const float* __restrict__ lab) {
    int b = blockIdx.y;
    int slot = blockIdx.x * 256 + threadIdx.x;
    int nfg = g_nfg[b];
    if (blockIdx.x * 256 >= nfg) return;

    __shared__ float sl[NM * 5];
    for (int i = threadIdx.x; i < NM * 5; i += 256)
        sl[i] = lab[b * NM * 5 + i];
    __syncthreads();
    int nv = g_ngt[b];

    if (slot >= nfg) return;
    int a = g_aidx[b * NA + slot];
    unsigned long long inb = g_inb[b * NA + slot];
    const float* row = outp + ((size_t)b * NA + a) * NO;

    float cx = row[0], cy = row[1], w = row[2], h = row[3], obj = row[4];
    float to = 1.0f + fexp(-obj);
    float q  = frsqrt(to);          // sqrt(sigmoid(obj))
    float lso = -0.5f * flog(to);

    float S = 0.0f;
    #pragma unroll 4
    for (int g = 0; g < NC; g += 5) {
        float prod = 1.0f;
        #pragma unroll
        for (int c = 0; c < 5; c++) {
            float x = row[5 + g + c];
            float t = 1.0f + fexp(-x);
            prod *= fmaf(-q, frsqrt(t), 1.0f);
        }
        S += flog(fmaxf(prod, 1e-30f));
    }

    float px1 = cx - 0.5f * w, px2 = cx + 0.5f * w;
    float py1 = cy - 0.5f * h, py2 = cy + 0.5f * h;
    float area_p = w * h;
    #pragma unroll 1
    for (int m = 0; m < nv; m++) {
        size_t off = ((size_t)b * NM + m) * NA + slot;
        float gx = sl[m*5+0], gy = sl[m*5+1], gw = sl[m*5+2], gh = sl[m*5+3];
        float hw = 0.5f * gw, hh = 0.5f * gh;
        float tlx = fmaxf(gx - hw, px1), brx = fminf(gx + hw, px2);
        float tly = fmaxf(gy - hh, py1), bry = fminf(gy + hh, py2);
        float ai = ((tlx < brx) && (tly < bry)) ? (brx - tlx) * (bry - tly) : 0.0f;
        float iouv = ai / (gw * gh + area_p - ai + 1e-16f);
        int c = (int)sl[m*5+4];
        float x = row[5 + c];
        float t = 1.0f + __expf(-x);
        float lg = __logf(t);
        float p = q * __frsqrt_rn(t);
        float lp  = fmaxf(lso - 0.5f * lg, -100.0f);
        float l1p = fmaxf(__logf(1.0f - p), -100.0f);
        float cls_cost = -(lp + S - l1p);
        float extra = ((inb >> m) & 1ull) ? 0.0f : 100000.0f;
        float cost = cls_cost - 3.0f * __logf(iouv + 1e-8f) + extra;
        g_iou[off] = iouv;
        g_cost[off] = cost;
    }
}

// -------------------------------------------------------------------------
// Block per (b,m): scan compacted columns -> sorted 10-lists -> merge tree.
__global__ void __launch_bounds__(ST) kselect() {
    int m = blockIdx.x, b = blockIdx.y;
    if (m >= g_ngt[b]) return;

    int n = g_nfg[b];
    size_t rowbase = ((size_t)b * NM + m) * NA;
    const float* iour  = g_iou  + rowbase;
    const float* costr = g_cost + rowbase;
    const int*   aidxr = g_aidx + b * NA;
    int t = threadIdx.x;

    float ti[10], tc[10];
    int   tx[10];
    #pragma unroll
    for (int k = 0; k < 10; k++) { ti[k] = 0.0f; tc[k] = 3.0e38f; tx[k] = 0x7fffffff; }

    for (int i = t; i < n; i += ST) {
        float v = iour[i];
        float c = costr[i];
        if (v > ti[9]) {
            float cur = v;
            #pragma unroll
            for (int k = 0; k < 10; k++)
                if (cur > ti[k]) { float tmp = ti[k]; ti[k] = cur; cur = tmp; }
        }
        if (c < tc[9]) {
            int ci = aidxr[i];
            float cv = c;
            #pragma unroll
            for (int k = 0; k < 10; k++) {
                bool sw = (cv < tc[k]) || (cv == tc[k] && ci < tx[k]);
                if (sw) {
                    float tf = tc[k]; tc[k] = cv; cv = tf;
                    int   tn = tx[k]; tx[k] = ci; ci = tn;
                }
            }
        }
    }

    __shared__ float s_v[ST * 10];
    __shared__ float s_c[ST * 10];
    __shared__ int   s_x[ST * 10];
    #pragma unroll
    for (int k = 0; k < 10; k++) {
        s_v[t * 10 + k] = ti[k];
        s_c[t * 10 + k] = tc[k];
        s_x[t * 10 + k] = tx[k];
    }
    __syncthreads();

    for (int stride = 1; stride < ST; stride <<= 1) {
        if ((t & (2 * stride - 1)) == 0) {
            int A = t * 10, B = (t + stride) * 10;
            {
                float M[10]; int i = 0, j = 0;
                #pragma unroll
                for (int k = 0; k < 10; k++) {
                    float av = s_v[A + i], bv = s_v[B + j];
                    if (av >= bv) { M[k] = av; i++; } else { M[k] = bv; j++; }
                }
                #pragma unroll
                for (int k = 0; k < 10; k++) s_v[A + k] = M[k];
            }
            {
                float Mc[10]; int Mx[10]; int i = 0, j = 0;
                #pragma unroll
                for (int k = 0; k < 10; k++) {
                    float ac = s_c[A + i], bc = s_c[B + j];
                    int   ax = s_x[A + i], bx = s_x[B + j];
                    bool takeA = (ac < bc) || (ac == bc && ax < bx);
                    if (takeA) { Mc[k] = ac; Mx[k] = ax; i++; }
                    else       { Mc[k] = bc; Mx[k] = bx; j++; }
                }
                #pragma unroll
                for (int k = 0; k < 10; k++) { s_c[A + k] = Mc[k]; s_x[A + k] = Mx[k]; }
            }
        }
        __syncthreads();
    }

    if (t == 0) {
        float ksum = 0.0f;
        #pragma unroll
        for (int k = 0; k < 10; k++) ksum += s_v[k];
        int dynk = (int)ksum;
        if (dynk < 1) dynk = 1;
        if (dynk > 10) dynk = 10;

        unsigned int ents[10];
        int ns = 0;
        for (int k = 0; k < dynk; k++) {
            if (s_c[k] >= BIGC) break;
            int a = s_x[k];
            atomicOr(&g_mask[b * NA + a], 1ull << m);
            ents[ns++] = ((unsigned int)b << 20) | ((unsigned int)m << 14) | (unsigned int)a;
        }
        if (ns > 0) {
            int base = atomicAdd(&g_cnt, ns);
            for (int k = 0; k < ns; k++) g_ent[base + k] = ents[k];
        }
    }
}

// -------------------------------------------------------------------------
__global__ void __launch_bounds__(256) klossC(const float* __restrict__ outp,
                                              const float* __restrict__ lab,
                                              float* __restrict__ out) {
    int idx = blockIdx.x * 256 + threadIdx.x;
    int cnt = g_cnt;
    float l_iou = 0.0f, l_obj = 0.0f, l_cls = 0.0f, nf = 0.0f;

    if (idx < NBLK) l_obj += g_pobj[idx];

    if (idx < cnt) {
        unsigned int e = g_ent[idx];
        int b = e >> 20;
        int m = (e >> 14) & 0x3f;
        int a = e & 0x3fff;
        unsigned long long mask = g_mask[b * NA + a];
        int first = __ffsll((long long)mask) - 1;
        if (m == first) {
            nf = 1.0f;
            int amg = __popcll(mask);
            const float* row = outp + ((size_t)b * NA + a) * NO;
            float obj = row[4];
            l_obj += -obj;

            int slot = g_slotOf[b * NA + a];
            int mgt;
            if (amg == 1) {
                mgt = first;
            } else {
                int ngt = g_ngt[b];
                float bv = 3.0e38f; mgt = 0;
                for (int mm = 0; mm < ngt; mm++) {
                    float c = g_cost[((size_t)b * NM + mm) * NA + slot];
                    if (c < bv) { bv = c; mgt = mm; }
                }
            }
            float pious = g_iou[((size_t)b * NM + mgt) * NA + slot];
            const float* lrow = lab + (b * NM + mgt) * 5;
            float gx = lrow[0], gy = lrow[1], gw = lrow[2], gh = lrow[3];
            int gc = (int)lrow[4];
            float cx = row[0], cy = row[1], w = row[2], h = row[3];
            float hw = 0.5f * gw, hh = 0.5f * gh, pw = 0.5f * w, ph = 0.5f * h;
            float tlx = fmaxf(gx - hw, cx - pw), brx = fminf(gx + hw, cx + pw);
            float tly = fmaxf(gy - hh, cy - ph), bry = fminf(gy + hh, cy + ph);
            float ai = ((tlx < brx) && (tly < bry)) ? (brx - tlx) * (bry - tly) : 0.0f;
            float iou = ai / (w * h + gw * gh - ai + 1e-16f);
            l_iou = 1.0f - iou * iou;

            float ssp = 0.0f;
            #pragma unroll 4
            for (int c = 0; c < NC; c++) {
                float x = row[5 + c];
                ssp += x + __logf(1.0f + __expf(-x));
            }
            l_cls = ssp - row[5 + gc] * pious;
        }
    }

    int lane = threadIdx.x & 31, wid = threadIdx.x >> 5;
    #pragma unroll
    for (int o = 16; o > 0; o >>= 1) {
        l_iou += __shfl_down_sync(0xffffffffu, l_iou, o);
        l_obj += __shfl_down_sync(0xffffffffu, l_obj, o);
        l_cls += __shfl_down_sync(0xffffffffu, l_cls, o);
        nf    += __shfl_down_sync(0xffffffffu, nf, o);
    }
    __shared__ float sred[8][4];
    if (lane == 0) {
        sred[wid][0] = l_iou; sred[wid][1] = l_obj;
        sred[wid][2] = l_cls; sred[wid][3] = nf;
    }
    __syncthreads();
    __shared__ bool isLast;
    if (threadIdx.x == 0) {
        float p0 = 0, p1 = 0, p2 = 0, p3 = 0;
        #pragma unroll
        for (int wq = 0; wq < 8; wq++) {
            p0 += sred[wq][0]; p1 += sred[wq][1];
            p2 += sred[wq][2]; p3 += sred[wq][3];
        }
        atomicAdd(&g_acc[0], (double)p0);
        atomicAdd(&g_acc[1], (double)p1);
        atomicAdd(&g_acc[2], (double)p2);
        atomicAdd(&g_acc[3], (double)p3);
        __threadfence();
        int v = atomicAdd(&g_done, 1);
        isLast = (v == LOSS_BLOCKS - 1);
    }
    __syncthreads();
    if (isLast && threadIdx.x == 0) {
        double nfg = g_acc[3];
        if (nfg < 1.0) nfg = 1.0;
        out[0] = (float)((5.0 * g_acc[0] + g_acc[1] + g_acc[2]) / nfg);
        g_acc[0] = 0.0; g_acc[1] = 0.0; g_acc[2] = 0.0; g_acc[3] = 0.0;
        g_cnt = 0; g_done = 0;
        #pragma unroll
        for (int bb = 0; bb < NB; bb++) g_nfg[bb] = 0;
    }
}

// -------------------------------------------------------------------------
extern "C" void kernel_launch(void* const* d_in, const int* in_sizes, int n_in,
                              void* d_out, int out_size) {
    const float* outp = (const float*)d_in[0];
    const float* xsh  = (const float*)d_in[1];
    const float* ysh  = (const float*)d_in[2];
    const float* est  = (const float*)d_in[3];
    const float* lab  = (const float*)d_in[4];
    (void)in_sizes; (void)n_in; (void)out_size;

    dim3 gA(GX, NB);
    kassignA<<<gA, 256>>>(outp, xsh, ysh, est, lab);

    kheavy<<<gA, 256>>>(outp, lab);

    dim3 gB(NM, NB);
    kselect<<<gB, ST>>>();

    klossC<<<LOSS_BLOCKS, 256>>>(outp, lab, (float*)d_out);
}

// round 10
// speedup vs baseline: 2.0515x; 1.0695x over previous
#include <cuda_runtime.h>
#include <cuda_bf16.h>

#define NB 32
#define NA 8400
#define NM 50
#define NC 80
#define NO 85
#define BIGC 1000000000.0f
#define GX 33
#define NBLK (GX * NB)
#define MAXENT 16384
#define LOSS_BLOCKS 64
#define ST 256                 // kselect threads

// ---- scratch ----
__device__ float g_cost[(size_t)NB * NM * NA];
__device__ float g_iou [(size_t)NB * NM * NA];
__device__ int   g_aidx[NB * NA];
__device__ unsigned long long g_inb[NB * NA];   // per-slot inboth mask
__device__ int   g_slotOf[NB * NA];
__device__ float g_ssp[NB * NA];                // per-slot sum softplus(cls)
__device__ unsigned long long g_mask[NB * NA];
__device__ float g_pobj[NBLK];
__device__ int g_ngt[NB];
__device__ int g_nfg[NB];              // zero-init; re-zeroed by klossC
__device__ unsigned int g_ent[MAXENT];
__device__ int g_cnt;
__device__ int g_done;
__device__ double g_acc[4];

// ---- FMA-pipe transcendentals ----
__device__ __forceinline__ float fexp(float x) {
    float t = x * 1.442695041f;
    float n = rintf(t);
    float g = fmaf(n, -0.6931471806f, t * 0.6931471806f);
    float p = 8.33333333e-3f;
    p = fmaf(p, g, 4.16666667e-2f);
    p = fmaf(p, g, 0.166666667f);
    p = fmaf(p, g, 0.5f);
    p = fmaf(p, g, 1.0f);
    p = fmaf(p, g, 1.0f);
    return p * __int_as_float(((int)n + 127) << 23);
}
__device__ __forceinline__ float flog(float x) {
    int xi = __float_as_int(x);
    int ei = ((xi >> 23) & 0xff) - 126;
    float m = __int_as_float((xi & 0x007fffff) | 0x3f000000);
    if (m < 0.70710678f) { m += m; ei -= 1; }
    float u = m - 1.0f;
    float z = u * u;
    float pp =  7.0376836292e-2f;
    pp = fmaf(pp, u, -1.1514610310e-1f);
    pp = fmaf(pp, u,  1.1676998740e-1f);
    pp = fmaf(pp, u, -1.2420140846e-1f);
    pp = fmaf(pp, u,  1.4249322787e-1f);
    pp = fmaf(pp, u, -1.6668057665e-1f);
    pp = fmaf(pp, u,  2.0000714765e-1f);
    pp = fmaf(pp, u, -2.4999993993e-1f);
    pp = fmaf(pp, u,  3.3333331174e-1f);
    float r = fmaf(pp * u, z, fmaf(-0.5f, z, u));
    return fmaf((float)ei, 0.69314718056f, r);
}
__device__ __forceinline__ float frsqrt(float x) {
    float r = __int_as_float(0x5f375a86 - (__float_as_int(x) >> 1));
    r = r * fmaf(-0.5f * x, r * r, 1.5f);
    r = r * fmaf(-0.5f * x, r * r, 1.5f);
    return r;
}

// -------------------------------------------------------------------------
// Phase 1: geometry, fg, compaction, objbase. Uniform light work.
__global__ void __launch_bounds__(256) kassignA(
        const float* __restrict__ outp,
        const float* __restrict__ xsh,
        const float* __restrict__ ysh,
        const float* __restrict__ est,
        const float* __restrict__ lab) {
    int b = blockIdx.y;
    __shared__ float sl[NM * 5];
    __shared__ int s_nv;
    __shared__ int wcnt[8];
    __shared__ int bbase;
    for (int i = threadIdx.x; i < NM * 5; i += 256)
        sl[i] = lab[b * NM * 5 + i];
    __syncthreads();
    if (threadIdx.x == 0) {
        int n = 0;
        for (int m = 0; m < NM; m++) {
            float s = sl[m*5+0] + sl[m*5+1] + sl[m*5+2] + sl[m*5+3] + sl[m*5+4];
            if (s > 0.0f) n++;
        }
        s_nv = n;
        if (blockIdx.x == 0) g_ngt[b] = n;
    }
    __syncthreads();
    int nv = s_nv;

    int tid = threadIdx.x;
    int lane = tid & 31, wid = tid >> 5;
    int a = blockIdx.x * 256 + tid;
    bool act = (a < NA);
    float objbase = 0.0f;

    bool fg = false;
    unsigned long long inboth = 0ull;

    if (act) {
        g_mask[b * NA + a] = 0ull;
        float stride = est[a];
        float xc = (xsh[a] + 0.5f) * stride;
        float yc = (ysh[a] + 0.5f) * stride;
        float rad = 2.5f * stride;
        float obj = outp[((size_t)b * NA + a) * NO + 4];
        objbase = fmaxf(obj, 0.0f) + __logf(1.0f + __expf(-fabsf(obj)));

        #pragma unroll 1
        for (int m = 0; m < nv; m++) {
            float gx = sl[m*5+0], gy = sl[m*5+1], gw = sl[m*5+2], gh = sl[m*5+3];
            float hw = 0.5f * gw, hh = 0.5f * gh;
            bool ib = (xc > gx - hw) && (gx + hw > xc) && (yc > gy - hh) && (gy + hh > yc);
            bool ic = (xc > gx - rad) && (xc < gx + rad) && (yc > gy - rad) && (yc < gy + rad);
            fg = fg || ib || ic;
            if (ib && ic) inboth |= 1ull << m;
        }
    }

    unsigned wm = __ballot_sync(0xffffffffu, fg);
    if (lane == 0) wcnt[wid] = __popc(wm);
    __syncthreads();
    if (tid == 0) {
        int s = 0;
        #pragma unroll
        for (int w = 0; w < 8; w++) { int c = wcnt[w]; wcnt[w] = s; s += c; }
        bbase = (s > 0) ? atomicAdd(&g_nfg[b], s) : 0;
    }
    __syncthreads();
    int rank = wcnt[wid] + __popc(wm & ((1u << lane) - 1u));

    if (fg) {
        int slot = bbase + rank;
        g_aidx[b * NA + slot] = a;
        g_inb[b * NA + slot] = inboth;
        g_slotOf[b * NA + a] = slot;
    }

    #pragma unroll
    for (int o = 16; o > 0; o >>= 1)
        objbase += __shfl_down_sync(0xffffffffu, objbase, o);
    __shared__ float sred[8];
    if (lane == 0) sred[wid] = objbase;
    __syncthreads();
    if (tid == 0) {
        float p = 0;
        #pragma unroll
        for (int wq = 0; wq < 8; wq++) p += sred[wq];
        g_pobj[blockIdx.y * GX + blockIdx.x] = p;
    }
}

// -------------------------------------------------------------------------
// Phase 2: heavy per-fg-anchor work over the compacted slot space. Uniform.
// Also accumulates ssp = sum_c softplus(x_c) for the cls loss.
__global__ void __launch_bounds__(256) kheavy(
        const float* __restrict__ outp,
        const float* __restrict__ lab) {
    int b = blockIdx.y;
    int slot = blockIdx.x * 256 + threadIdx.x;
    int nfg = g_nfg[b];
    if (blockIdx.x * 256 >= nfg) return;

    __shared__ float sl[NM * 5];
    for (int i = threadIdx.x; i < NM * 5; i += 256)
        sl[i] = lab[b * NM * 5 + i];
    __syncthreads();
    int nv = g_ngt[b];

    if (slot >= nfg) return;
    int a = g_aidx[b * NA + slot];
    unsigned long long inb = g_inb[b * NA + slot];
    const float* row = outp + ((size_t)b * NA + a) * NO;

    float cx = row[0], cy = row[1], w = row[2], h = row[3], obj = row[4];
    float to = 1.0f + fexp(-obj);
    float q  = frsqrt(to);          // sqrt(sigmoid(obj))
    float lso = -0.5f * flog(to);

    float S = 0.0f, ssp = 0.0f;
    #pragma unroll 4
    for (int g = 0; g < NC; g += 5) {
        float prod = 1.0f, pt = 1.0f, sx = 0.0f;
        #pragma unroll
        for (int c = 0; c < 5; c++) {
            float x = row[5 + g + c];
            float t = 1.0f + fexp(-x);
            pt *= t;
            sx += x;
            prod *= fmaf(-q, frsqrt(t), 1.0f);
        }
        S += flog(fmaxf(prod, 1e-30f));
        ssp += sx + flog(pt);       // sum softplus over the group
    }
    g_ssp[b * NA + slot] = ssp;

    float px1 = cx - 0.5f * w, px2 = cx + 0.5f * w;
    float py1 = cy - 0.5f * h, py2 = cy + 0.5f * h;
    float area_p = w * h;
    #pragma unroll 1
    for (int m = 0; m < nv; m++) {
        size_t off = ((size_t)b * NM + m) * NA + slot;
        float gx = sl[m*5+0], gy = sl[m*5+1], gw = sl[m*5+2], gh = sl[m*5+3];
        float hw = 0.5f * gw, hh = 0.5f * gh;
        float tlx = fmaxf(gx - hw, px1), brx = fminf(gx + hw, px2);
        float tly = fmaxf(gy - hh, py1), bry = fminf(gy + hh, py2);
        float ai = ((tlx < brx) && (tly < bry)) ? (brx - tlx) * (bry - tly) : 0.0f;
        float iouv = ai / (gw * gh + area_p - ai + 1e-16f);
        int c = (int)sl[m*5+4];
        float x = row[5 + c];
        float t = 1.0f + __expf(-x);
        float lg = __logf(t);
        float p = q * __frsqrt_rn(t);
        float lp  = fmaxf(lso - 0.5f * lg, -100.0f);
        float l1p = fmaxf(__logf(1.0f - p), -100.0f);
        float cls_cost = -(lp + S - l1p);
        float extra = ((inb >> m) & 1ull) ? 0.0f : 100000.0f;
        float cost = cls_cost - 3.0f * __logf(iouv + 1e-8f) + extra;
        g_iou[off] = iouv;
        g_cost[off] = cost;
    }
}

// -------------------------------------------------------------------------
// Block per (b,m): scan compacted columns -> sorted 10-lists -> merge tree.
__global__ void __launch_bounds__(ST) kselect() {
    int m = blockIdx.x, b = blockIdx.y;
    if (m >= g_ngt[b]) return;

    int n = g_nfg[b];
    size_t rowbase = ((size_t)b * NM + m) * NA;
    const float* iour  = g_iou  + rowbase;
    const float* costr = g_cost + rowbase;
    const int*   aidxr = g_aidx + b * NA;
    int t = threadIdx.x;

    float ti[10], tc[10];
    int   tx[10];
    #pragma unroll
    for (int k = 0; k < 10; k++) { ti[k] = 0.0f; tc[k] = 3.0e38f; tx[k] = 0x7fffffff; }

    for (int i = t; i < n; i += ST) {
        float v = iour[i];
        float c = costr[i];
        if (v > ti[9]) {
            float cur = v;
            #pragma unroll
            for (int k = 0; k < 10; k++)
                if (cur > ti[k]) { float tmp = ti[k]; ti[k] = cur; cur = tmp; }
        }
        if (c < tc[9]) {
            int ci = aidxr[i];
            float cv = c;
            #pragma unroll
            for (int k = 0; k < 10; k++) {
                bool sw = (cv < tc[k]) || (cv == tc[k] && ci < tx[k]);
                if (sw) {
                    float tf = tc[k]; tc[k] = cv; cv = tf;
                    int   tn = tx[k]; tx[k] = ci; ci = tn;
                }
            }
        }
    }

    __shared__ float s_v[ST * 10];
    __shared__ float s_c[ST * 10];
    __shared__ int   s_x[ST * 10];
    #pragma unroll
    for (int k = 0; k < 10; k++) {
        s_v[t * 10 + k] = ti[k];
        s_c[t * 10 + k] = tc[k];
        s_x[t * 10 + k] = tx[k];
    }
    __syncthreads();

    for (int stride = 1; stride < ST; stride <<= 1) {
        if ((t & (2 * stride - 1)) == 0) {
            int A = t * 10, B = (t + stride) * 10;
            {
                float M[10]; int i = 0, j = 0;
                #pragma unroll
                for (int k = 0; k < 10; k++) {
                    float av = s_v[A + i], bv = s_v[B + j];
                    if (av >= bv) { M[k] = av; i++; } else { M[k] = bv; j++; }
                }
                #pragma unroll
                for (int k = 0; k < 10; k++) s_v[A + k] = M[k];
            }
            {
                float Mc[10]; int Mx[10]; int i = 0, j = 0;
                #pragma unroll
                for (int k = 0; k < 10; k++) {
                    float ac = s_c[A + i], bc = s_c[B + j];
                    int   ax = s_x[A + i], bx = s_x[B + j];
                    bool takeA = (ac < bc) || (ac == bc && ax < bx);
                    if (takeA) { Mc[k] = ac; Mx[k] = ax; i++; }
                    else       { Mc[k] = bc; Mx[k] = bx; j++; }
                }
                #pragma unroll
                for (int k = 0; k < 10; k++) { s_c[A + k] = Mc[k]; s_x[A + k] = Mx[k]; }
            }
        }
        __syncthreads();
    }

    if (t == 0) {
        float ksum = 0.0f;
        #pragma unroll
        for (int k = 0; k < 10; k++) ksum += s_v[k];
        int dynk = (int)ksum;
        if (dynk < 1) dynk = 1;
        if (dynk > 10) dynk = 10;

        unsigned int ents[10];
        int ns = 0;
        for (int k = 0; k < dynk; k++) {
            if (s_c[k] >= BIGC) break;
            int a = s_x[k];
            atomicOr(&g_mask[b * NA + a], 1ull << m);
            ents[ns++] = ((unsigned int)b << 20) | ((unsigned int)m << 14) | (unsigned int)a;
        }
        if (ns > 0) {
            int base = atomicAdd(&g_cnt, ns);
            for (int k = 0; k < ns; k++) g_ent[base + k] = ents[k];
        }
    }
}

// -------------------------------------------------------------------------
__global__ void __launch_bounds__(256) klossC(const float* __restrict__ outp,
                                              const float* __restrict__ lab,
                                              float* __restrict__ out) {
    int idx = blockIdx.x * 256 + threadIdx.x;
    int cnt = g_cnt;
    float l_iou = 0.0f, l_obj = 0.0f, l_cls = 0.0f, nf = 0.0f;

    if (idx < NBLK) l_obj += g_pobj[idx];

    if (idx < cnt) {
        unsigned int e = g_ent[idx];
        int b = e >> 20;
        int m = (e >> 14) & 0x3f;
        int a = e & 0x3fff;
        unsigned long long mask = g_mask[b * NA + a];
        int first = __ffsll((long long)mask) - 1;
        if (m == first) {
            nf = 1.0f;
            int amg = __popcll(mask);
            const float* row = outp + ((size_t)b * NA + a) * NO;
            float obj = row[4];
            l_obj += -obj;

            int slot = g_slotOf[b * NA + a];
            int mgt;
            if (amg == 1) {
                mgt = first;
            } else {
                int ngt = g_ngt[b];
                float bv = 3.0e38f; mgt = 0;
                for (int mm = 0; mm < ngt; mm++) {
                    float c = g_cost[((size_t)b * NM + mm) * NA + slot];
                    if (c < bv) { bv = c; mgt = mm; }
                }
            }
            float pious = g_iou[((size_t)b * NM + mgt) * NA + slot];
            const float* lrow = lab + (b * NM + mgt) * 5;
            float gx = lrow[0], gy = lrow[1], gw = lrow[2], gh = lrow[3];
            int gc = (int)lrow[4];
            float cx = row[0], cy = row[1], w = row[2], h = row[3];
            float hw = 0.5f * gw, hh = 0.5f * gh, pw = 0.5f * w, ph = 0.5f * h;
            float tlx = fmaxf(gx - hw, cx - pw), brx = fminf(gx + hw, cx + pw);
            float tly = fmaxf(gy - hh, cy - ph), bry = fminf(gy + hh, cy + ph);
            float ai = ((tlx < brx) && (tly < bry)) ? (brx - tlx) * (bry - tly) : 0.0f;
            float iou = ai / (w * h + gw * gh - ai + 1e-16f);
            l_iou = 1.0f - iou * iou;

            l_cls = g_ssp[b * NA + slot] - row[5 + gc] * pious;
        }
    }

    int lane = threadIdx.x & 31, wid = threadIdx.x >> 5;
    #pragma unroll
    for (int o = 16; o > 0; o >>= 1) {
        l_iou += __shfl_down_sync(0xffffffffu, l_iou, o);
        l_obj += __shfl_down_sync(0xffffffffu, l_obj, o);
        l_cls += __shfl_down_sync(0xffffffffu, l_cls, o);
        nf    += __shfl_down_sync(0xffffffffu, nf, o);
    }
    __shared__ float sred[8][4];
    if (lane == 0) {
        sred[wid][0] = l_iou; sred[wid][1] = l_obj;
        sred[wid][2] = l_cls; sred[wid][3] = nf;
    }
    __syncthreads();
    __shared__ bool isLast;
    if (threadIdx.x == 0) {
        float p0 = 0, p1 = 0, p2 = 0, p3 = 0;
        #pragma unroll
        for (int wq = 0; wq < 8; wq++) {
            p0 += sred[wq][0]; p1 += sred[wq][1];
            p2 += sred[wq][2]; p3 += sred[wq][3];
        }
        atomicAdd(&g_acc[0], (double)p0);
        atomicAdd(&g_acc[1], (double)p1);
        atomicAdd(&g_acc[2], (double)p2);
        atomicAdd(&g_acc[3], (double)p3);
        __threadfence();
        int v = atomicAdd(&g_done, 1);
        isLast = (v == LOSS_BLOCKS - 1);
    }
    __syncthreads();
    if (isLast && threadIdx.x == 0) {
        double nfg = g_acc[3];
        if (nfg < 1.0) nfg = 1.0;
        out[0] = (float)((5.0 * g_acc[0] + g_acc[1] + g_acc[2]) / nfg);
        g_acc[0] = 0.0; g_acc[1] = 0.0; g_acc[2] = 0.0; g_acc[3] = 0.0;
        g_cnt = 0; g_done = 0;
        #pragma unroll
        for (int bb = 0; bb < NB; bb++) g_nfg[bb] = 0;
    }
}

// -------------------------------------------------------------------------
extern "C" void kernel_launch(void* const* d_in, const int* in_sizes, int n_in,
                              void* d_out, int out_size) {
    const float* outp = (const float*)d_in[0];
    const float* xsh  = (const float*)d_in[1];
    const float* ysh  = (const float*)d_in[2];
    const float* est  = (const float*)d_in[3];
    const float* lab  = (const float*)d_in[4];
    (void)in_sizes; (void)n_in; (void)out_size;

    dim3 gA(GX, NB);
    kassignA<<<gA, 256>>>(outp, xsh, ysh, est, lab);

    kheavy<<<gA, 256>>>(outp, lab);

    dim3 gB(NM, NB);
    kselect<<<gB, ST>>>();

    klossC<<<LOSS_BLOCKS, 256>>>(outp, lab, (float*)d_out);
}